// round 5
// baseline (speedup 1.0000x reference)
#include <cuda_runtime.h>
#include <math.h>

// ---------------- problem constants ----------------
#define BATCH   32
#define HDIM    56
#define WDIM    56
#define CCH     256
#define HEADS   8
#define HD      32          // head dim
#define WS      7
#define SS      3
#define NTOK    49          // WS*WS
#define NWIN_IMG 64         // (56/7)^2
#define NWIN    (BATCH*NWIN_IMG)      // 2048
#define ROWS    (NWIN*NTOK)           // 100352 == BATCH*H*W
#define MLPD    1024

// ---------------- scratch (device globals; no allocation allowed) ----------------
__device__ float g_xw  [ (size_t)ROWS*CCH  ];   // LN1 + shifted + windowed       (~103 MB)
__device__ float g_qkv [ (size_t)ROWS*768  ];   // qkv projections                (~308 MB)
__device__ float g_attn[ (size_t)ROWS*CCH  ];   // attention output (win layout)  (~103 MB)
__device__ float g_x2  [ (size_t)ROWS*CCH  ];   // x + attn branch (image layout) (~103 MB)
__device__ float g_y2  [ (size_t)ROWS*CCH  ];   // LN2(x2)                        (~103 MB)
__device__ float g_h   [ (size_t)ROWS*MLPD ];   // gelu(fc1)                      (~411 MB)

// ---------------- helpers ----------------
__device__ __forceinline__ float warp_sum(float v) {
    #pragma unroll
    for (int o = 16; o > 0; o >>= 1) v += __shfl_xor_sync(0xffffffffu, v, o);
    return v;
}

// map a window-layout row (win*49+n) to the image-layout row (b*3136 + oy*56 + ox)
__device__ __forceinline__ int permuted_row(int row) {
    int win = row / NTOK, n = row - win * NTOK;
    int b  = win >> 6;          // /64
    int w  = win & 63;
    int wy = w >> 3, wx = w & 7;
    int r  = n / WS, c = n - r * WS;
    int oy = (wy * WS + r + SS) % HDIM;
    int ox = (wx * WS + c + SS) % WDIM;
    return b * (HDIM * WDIM) + oy * WDIM + ox;
}

// ---------------- LN kernel: warp per row ----------------
// permute==1: gather image row through shift+window map, write window layout (LN1)
// permute==0: identity rows (LN2)
__global__ __launch_bounds__(256)
void ln_kernel(const float* __restrict__ x, const float* __restrict__ sc,
               const float* __restrict__ bi, float* __restrict__ out, int permute)
{
    int row = blockIdx.x * 8 + threadIdx.y;
    if (row >= ROWS) return;
    int lane = threadIdx.x;

    int irow = permute ? permuted_row(row) : row;

    const float4* xr = (const float4*)(x + (size_t)irow * CCH);
    float4 v0 = xr[lane];
    float4 v1 = xr[lane + 32];

    float s  = v0.x + v0.y + v0.z + v0.w + v1.x + v1.y + v1.z + v1.w;
    float sq = v0.x*v0.x + v0.y*v0.y + v0.z*v0.z + v0.w*v0.w
             + v1.x*v1.x + v1.y*v1.y + v1.z*v1.z + v1.w*v1.w;
    s  = warp_sum(s);
    sq = warp_sum(sq);
    float mu  = s * (1.f / CCH);
    float var = sq * (1.f / CCH) - mu * mu;
    float rs  = rsqrtf(var + 1e-6f);

    int c0 = lane * 4, c1 = 128 + lane * 4;
    float4 o0, o1;
    o0.x = (v0.x - mu) * rs * sc[c0+0] + bi[c0+0];
    o0.y = (v0.y - mu) * rs * sc[c0+1] + bi[c0+1];
    o0.z = (v0.z - mu) * rs * sc[c0+2] + bi[c0+2];
    o0.w = (v0.w - mu) * rs * sc[c0+3] + bi[c0+3];
    o1.x = (v1.x - mu) * rs * sc[c1+0] + bi[c1+0];
    o1.y = (v1.y - mu) * rs * sc[c1+1] + bi[c1+1];
    o1.z = (v1.z - mu) * rs * sc[c1+2] + bi[c1+2];
    o1.w = (v1.w - mu) * rs * sc[c1+3] + bi[c1+3];
    float4* orow = (float4*)(out + (size_t)row * CCH);
    orow[lane]      = o0;
    orow[lane + 32] = o1;
}

// ---------------- SGEMM 128x128x8, 8x8 microtile, 256 threads ----------------
// MODE 0: C = A@B + bias                       (QKV)
// MODE 1: C[perm(row)] = A@B + bias + res[perm(row)]   (proj + window reverse + residual)
// MODE 2: C = gelu(A@B + bias)                 (fc1)
// MODE 3: C = A@B + bias + res[row]            (fc2 + residual -> d_out)
// All dims divide the tile sizes exactly (M=100352, N in {256,768,1024}, K in {256,1024}).
template<int MODE>
__global__ __launch_bounds__(256)
void sgemm(int M, int N, int K,
           const float* __restrict__ A, const float* __restrict__ B,
           const float* __restrict__ bias, const float* __restrict__ res,
           float* __restrict__ C)
{
    constexpr int BM = 128, BN = 128, BK = 8, TM = 8, TN = 8;
    __shared__ float As[BK * BM];   // transposed: As[k*BM + m]
    __shared__ float Bs[BK * BN];

    const int cRow = blockIdx.y, cCol = blockIdx.x;
    const int tid = threadIdx.x;
    const int threadCol = tid % (BN / TN);   // 0..15
    const int threadRow = tid / (BN / TN);   // 0..15

    A += (size_t)cRow * BM * K;
    B += cCol * BN;

    const int innerRowA = tid / (BK / 4);    // tid/2 : 0..127
    const int innerColA = tid % (BK / 4);    // 0..1
    const int innerRowB = tid / (BN / 4);    // tid/32: 0..7
    const int innerColB = tid % (BN / 4);    // 0..31

    float acc[TM * TN] = {0.f};
    float regM[TM], regN[TN];

    for (int k0 = 0; k0 < K; k0 += BK) {
        float4 a = *(const float4*)(A + (size_t)innerRowA * K + innerColA * 4);
        As[(innerColA * 4 + 0) * BM + innerRowA] = a.x;
        As[(innerColA * 4 + 1) * BM + innerRowA] = a.y;
        As[(innerColA * 4 + 2) * BM + innerRowA] = a.z;
        As[(innerColA * 4 + 3) * BM + innerRowA] = a.w;
        *(float4*)(&Bs[innerRowB * BN + innerColB * 4]) =
            *(const float4*)(B + (size_t)innerRowB * N + innerColB * 4);
        __syncthreads();
        A += BK;
        B += (size_t)BK * N;
        #pragma unroll
        for (int k = 0; k < BK; k++) {
            #pragma unroll
            for (int i = 0; i < TM; i++) regM[i] = As[k * BM + threadRow * TM + i];
            #pragma unroll
            for (int j = 0; j < TN; j++) regN[j] = Bs[k * BN + threadCol * TN + j];
            #pragma unroll
            for (int i = 0; i < TM; i++)
                #pragma unroll
                for (int j = 0; j < TN; j++)
                    acc[i * TN + j] += regM[i] * regN[j];
        }
        __syncthreads();
    }

    // epilogue
    #pragma unroll
    for (int i = 0; i < TM; i++) {
        int row = cRow * BM + threadRow * TM + i;
        int orow = row;
        if (MODE == 1) orow = permuted_row(row);
        #pragma unroll
        for (int j = 0; j < TN; j++) {
            int col = cCol * BN + threadCol * TN + j;
            float v = acc[i * TN + j] + bias[col];
            if (MODE == 1) {
                v += res[(size_t)orow * N + col];
            } else if (MODE == 2) {
                float y = v;
                v = 0.5f * y * (1.f + tanhf(0.7978845608028654f * (y + 0.044715f * y * y * y)));
            } else if (MODE == 3) {
                v += res[(size_t)row * N + col];
            }
            C[(size_t)orow * N + col] = v;
        }
    }
}

// ---------------- attention: one block per (window, head) ----------------
__global__ __launch_bounds__(256)
void attn_kernel(const float* __restrict__ qkv, const float* __restrict__ bias_table,
                 float* __restrict__ out)
{
    const int blk  = blockIdx.x;
    const int win  = blk >> 3;
    const int head = blk & 7;
    const int w    = win & 63;
    const int wy   = w >> 3, wx = w & 7;

    __shared__ float sq[NTOK * 33];
    __shared__ float sk[NTOK * 33];
    __shared__ float sv[NTOK * 33];
    __shared__ float S [NTOK * 50];
    __shared__ float sb[169];
    __shared__ int   sreg[NTOK];

    const int tid = threadIdx.x;

    for (int i = tid; i < 169; i += 256) sb[i] = bias_table[i * HEADS + head];
    if (tid < NTOK) {
        int r = tid / WS, c = tid - r * WS;
        int sy = wy * WS + r, sx = wx * WS + c;
        int ry = (sy < HDIM - WS) ? 0 : ((sy < HDIM - SS) ? 1 : 2);
        int rx = (sx < WDIM - WS) ? 0 : ((sx < WDIM - SS) ? 1 : 2);
        sreg[tid] = ry * 3 + rx;
    }

    const float scale = 0.17677669529663687f;  // 32^-0.5
    for (int i = tid; i < NTOK * HD; i += 256) {
        int n = i >> 5, dd = i & 31;
        const float* base = qkv + ((size_t)(win * NTOK + n)) * 768 + head * HD + dd;
        sq[n * 33 + dd] = base[0] * scale;
        sk[n * 33 + dd] = base[256];
        sv[n * 33 + dd] = base[512];
    }
    __syncthreads();

    // S = q @ k^T + rpb + mask
    for (int p = tid; p < NTOK * NTOK; p += 256) {
        int n1 = p / NTOK, n2 = p - n1 * NTOK;
        float s = 0.f;
        #pragma unroll
        for (int t = 0; t < HD; t++) s += sq[n1 * 33 + t] * sk[n2 * 33 + t];
        int r1 = n1 / WS, c1 = n1 - r1 * WS;
        int r2 = n2 / WS, c2 = n2 - r2 * WS;
        s += sb[(c1 - c2 + WS - 1) * (2 * WS - 1) + (r1 - r2 + WS - 1)];
        if (sreg[n1] != sreg[n2]) s -= 100.f;
        S[n1 * 50 + n2] = s;
    }
    __syncthreads();

    // softmax: warp per row
    int warp = tid >> 5, lane = tid & 31;
    for (int n1 = warp; n1 < NTOK; n1 += 8) {
        float a0 = S[n1 * 50 + lane];
        float a1 = (lane + 32 < NTOK) ? S[n1 * 50 + lane + 32] : -1e30f;
        float m = fmaxf(a0, a1);
        #pragma unroll
        for (int o = 16; o > 0; o >>= 1) m = fmaxf(m, __shfl_xor_sync(0xffffffffu, m, o));
        float e0 = __expf(a0 - m);
        float e1 = (lane + 32 < NTOK) ? __expf(a1 - m) : 0.f;
        float ss = warp_sum(e0 + e1);
        float inv = 1.f / ss;
        S[n1 * 50 + lane] = e0 * inv;
        if (lane + 32 < NTOK) S[n1 * 50 + lane + 32] = e1 * inv;
    }
    __syncthreads();

    // out = P @ V  ->  (win,n,head*32+dd) layout
    for (int p = tid; p < NTOK * HD; p += 256) {
        int n1 = p >> 5, dd = p & 31;
        float o = 0.f;
        #pragma unroll
        for (int j = 0; j < NTOK; j++) o += S[n1 * 50 + j] * sv[j * 33 + dd];
        out[((size_t)(win * NTOK + n1)) * CCH + head * HD + dd] = o;
    }
}

// ---------------- launch ----------------
extern "C" void kernel_launch(void* const* d_in, const int* in_sizes, int n_in,
                              void* d_out, int out_size)
{
    const float* x         = (const float*)d_in[0];
    const float* ln1_scale = (const float*)d_in[1];
    const float* ln1_bias  = (const float*)d_in[2];
    const float* qkv_w     = (const float*)d_in[3];
    const float* qkv_b     = (const float*)d_in[4];
    const float* proj_w    = (const float*)d_in[5];
    const float* proj_b    = (const float*)d_in[6];
    const float* bias_tbl  = (const float*)d_in[7];
    const float* ln2_scale = (const float*)d_in[8];
    const float* ln2_bias  = (const float*)d_in[9];
    const float* fc1_w     = (const float*)d_in[10];
    const float* fc1_b     = (const float*)d_in[11];
    const float* fc2_w     = (const float*)d_in[12];
    const float* fc2_b     = (const float*)d_in[13];
    float* out = (float*)d_out;

    float *xw, *qkv, *attn, *x2, *y2, *hbuf;
    cudaGetSymbolAddress((void**)&xw,   g_xw);
    cudaGetSymbolAddress((void**)&qkv,  g_qkv);
    cudaGetSymbolAddress((void**)&attn, g_attn);
    cudaGetSymbolAddress((void**)&x2,   g_x2);
    cudaGetSymbolAddress((void**)&y2,   g_y2);
    cudaGetSymbolAddress((void**)&hbuf, g_h);

    dim3 lnBlk(32, 8);
    int  lnGrid = ROWS / 8;   // 12544

    // 1. LN1 + shift + window partition
    ln_kernel<<<lnGrid, lnBlk>>>(x, ln1_scale, ln1_bias, xw, 1);
    // 2. QKV gemm: (100352 x 256) @ (256 x 768)
    sgemm<0><<<dim3(768 / 128, ROWS / 128), 256>>>(ROWS, 768, 256, xw, qkv_w, qkv_b, nullptr, qkv);
    // 3. attention per (window, head)
    attn_kernel<<<NWIN * HEADS, 256>>>(qkv, bias_tbl, attn);
    // 4. proj gemm + window reverse + unshift + residual -> x2 (image layout)
    sgemm<1><<<dim3(256 / 128, ROWS / 128), 256>>>(ROWS, 256, 256, attn, proj_w, proj_b, x, x2);
    // 5. LN2
    ln_kernel<<<lnGrid, lnBlk>>>(x2, ln2_scale, ln2_bias, y2, 0);
    // 6. fc1 + gelu
    sgemm<2><<<dim3(1024 / 128, ROWS / 128), 256>>>(ROWS, 1024, 256, y2, fc1_w, fc1_b, nullptr, hbuf);
    // 7. fc2 + residual -> out
    sgemm<3><<<dim3(256 / 128, ROWS / 128), 256>>>(ROWS, 256, 1024, hbuf, fc2_w, fc2_b, x2, out);
}

// round 7
// speedup vs baseline: 2.3038x; 2.3038x over previous
#include <cuda_runtime.h>
#include <math.h>

// ---------------- problem constants ----------------
#define BATCH   32
#define HDIM    56
#define WDIM    56
#define CCH     256
#define HEADS   8
#define HD      32          // head dim
#define WS      7
#define SS      3
#define NTOK    49          // WS*WS
#define NWIN_IMG 64         // (56/7)^2
#define NWIN    (BATCH*NWIN_IMG)      // 2048
#define ROWS    (NWIN*NTOK)           // 100352 == BATCH*H*W
#define MLPD    1024

// ---------------- scratch (device globals; no allocation allowed) ----------------
__device__ float g_xw  [ (size_t)ROWS*CCH  ];   // LN1 + shifted + windowed
__device__ float g_qkv [ (size_t)ROWS*768  ];   // qkv projections
__device__ float g_attn[ (size_t)ROWS*CCH  ];   // attention output (win layout)
__device__ float g_x2  [ (size_t)ROWS*CCH  ];   // x + attn branch (image layout)
__device__ float g_y2  [ (size_t)ROWS*CCH  ];   // LN2(x2)
__device__ float g_h   [ (size_t)ROWS*MLPD ];   // gelu(fc1)

// ---------------- helpers ----------------
__device__ __forceinline__ float warp_sum(float v) {
    #pragma unroll
    for (int o = 16; o > 0; o >>= 1) v += __shfl_xor_sync(0xffffffffu, v, o);
    return v;
}

__device__ __forceinline__ unsigned f2tf32(float x) {
    unsigned u;
    asm("cvt.rna.tf32.f32 %0, %1;" : "=r"(u) : "f"(x));
    return u;
}

__device__ __forceinline__ void mma_tf32(float* c, const unsigned* a, const unsigned* b) {
    asm volatile(
        "mma.sync.aligned.m16n8k8.row.col.f32.tf32.tf32.f32 "
        "{%0,%1,%2,%3}, {%4,%5,%6,%7}, {%8,%9}, {%0,%1,%2,%3};\n"
        : "+f"(c[0]), "+f"(c[1]), "+f"(c[2]), "+f"(c[3])
        : "r"(a[0]), "r"(a[1]), "r"(a[2]), "r"(a[3]), "r"(b[0]), "r"(b[1]));
}

// map a window-layout row (win*49+n) to the image-layout row (b*3136 + oy*56 + ox)
__device__ __forceinline__ int permuted_row(int row) {
    int win = row / NTOK, n = row - win * NTOK;
    int b  = win >> 6;
    int w  = win & 63;
    int wy = w >> 3, wx = w & 7;
    int r  = n / WS, c = n - r * WS;
    int oy = (wy * WS + r + SS) % HDIM;
    int ox = (wx * WS + c + SS) % WDIM;
    return b * (HDIM * WDIM) + oy * WDIM + ox;
}

// ---------------- LN kernel: warp per row ----------------
__global__ __launch_bounds__(256)
void ln_kernel(const float* __restrict__ x, const float* __restrict__ sc,
               const float* __restrict__ bi, float* __restrict__ out, int permute)
{
    int row = blockIdx.x * 8 + threadIdx.y;
    if (row >= ROWS) return;
    int lane = threadIdx.x;

    int irow = permute ? permuted_row(row) : row;

    const float4* xr = (const float4*)(x + (size_t)irow * CCH);
    float4 v0 = xr[lane];
    float4 v1 = xr[lane + 32];

    float s  = v0.x + v0.y + v0.z + v0.w + v1.x + v1.y + v1.z + v1.w;
    float sq = v0.x*v0.x + v0.y*v0.y + v0.z*v0.z + v0.w*v0.w
             + v1.x*v1.x + v1.y*v1.y + v1.z*v1.z + v1.w*v1.w;
    s  = warp_sum(s);
    sq = warp_sum(sq);
    float mu  = s * (1.f / CCH);
    float var = sq * (1.f / CCH) - mu * mu;
    float rs  = rsqrtf(var + 1e-6f);

    int c0 = lane * 4, c1 = 128 + lane * 4;
    float4 o0, o1;
    o0.x = (v0.x - mu) * rs * sc[c0+0] + bi[c0+0];
    o0.y = (v0.y - mu) * rs * sc[c0+1] + bi[c0+1];
    o0.z = (v0.z - mu) * rs * sc[c0+2] + bi[c0+2];
    o0.w = (v0.w - mu) * rs * sc[c0+3] + bi[c0+3];
    o1.x = (v1.x - mu) * rs * sc[c1+0] + bi[c1+0];
    o1.y = (v1.y - mu) * rs * sc[c1+1] + bi[c1+1];
    o1.z = (v1.z - mu) * rs * sc[c1+2] + bi[c1+2];
    o1.w = (v1.w - mu) * rs * sc[c1+3] + bi[c1+3];
    float4* orow = (float4*)(out + (size_t)row * CCH);
    orow[lane]      = o0;
    orow[lane + 32] = o1;
}

// ---------------- TF32 tensor-core GEMM 128x128x16, 8 warps, fp32 accum --------
// MODE 0: C = A@B + bias                                (QKV)
// MODE 1: C[perm(row)] = A@B + bias + res[perm(row)]    (proj + reverse + residual)
// MODE 2: C = gelu(A@B + bias)                          (fc1)
// MODE 3: C = A@B + bias + res[row]                     (fc2 + residual -> out)
// M = ROWS (divisible by 128); N, K compile-time, divisible by 128/16.
template<int MODE, int N, int K>
__global__ __launch_bounds__(256)
void mma_gemm(const float* __restrict__ A, const float* __restrict__ B,
              const float* __restrict__ bias, const float* __restrict__ res,
              float* __restrict__ C)
{
    constexpr int BK = 16;
    constexpr int SSTR = 136;                 // smem stride (pad 8) -> conflict-free frags
    __shared__ unsigned sA[2][BK * SSTR];     // [k][m], tf32 patterns
    __shared__ unsigned sB[2][BK * SSTR];     // [k][n]

    const int tid  = threadIdx.x;
    const int lane = tid & 31;
    const int warp = tid >> 5;
    const int wm = (warp >> 2) * 64;          // warp row base in tile
    const int wn = (warp & 3) * 32;           // warp col base in tile
    const size_t blockM = (size_t)blockIdx.y * 128;
    const int    blockN = blockIdx.x * 128;

    // global load mapping
    const int aR = tid >> 2;                  // 0..63 (and +64)
    const int aC = (tid & 3) * 4;             // k offset 0..12
    const int bR = tid >> 5;                  // 0..7  (and +8)
    const int bC = (tid & 31) * 4;            // 0..124

    const float* Aptr = A + (blockM + aR) * K + aC;
    const float* Bptr = B + (size_t)bR * N + blockN + bC;

    float acc[4][4][4];
    #pragma unroll
    for (int i = 0; i < 4; i++)
        #pragma unroll
        for (int j = 0; j < 4; j++)
            #pragma unroll
            for (int k = 0; k < 4; k++) acc[i][j][k] = 0.f;

    const int gr = lane >> 2;                 // groupID
    const int gc = lane & 3;                  // threadID_in_group

    // ---- prologue: load tile 0 into buffer 0 ----
    float4 a0 = *(const float4*)(Aptr);
    float4 a1 = *(const float4*)(Aptr + (size_t)64 * K);
    float4 b0 = *(const float4*)(Bptr);
    float4 b1 = *(const float4*)(Bptr + (size_t)8 * N);
    {
        sA[0][(aC+0)*SSTR + aR]      = f2tf32(a0.x);
        sA[0][(aC+1)*SSTR + aR]      = f2tf32(a0.y);
        sA[0][(aC+2)*SSTR + aR]      = f2tf32(a0.z);
        sA[0][(aC+3)*SSTR + aR]      = f2tf32(a0.w);
        sA[0][(aC+0)*SSTR + aR+64]   = f2tf32(a1.x);
        sA[0][(aC+1)*SSTR + aR+64]   = f2tf32(a1.y);
        sA[0][(aC+2)*SSTR + aR+64]   = f2tf32(a1.z);
        sA[0][(aC+3)*SSTR + aR+64]   = f2tf32(a1.w);
        uint4 u0 = { f2tf32(b0.x), f2tf32(b0.y), f2tf32(b0.z), f2tf32(b0.w) };
        uint4 u1 = { f2tf32(b1.x), f2tf32(b1.y), f2tf32(b1.z), f2tf32(b1.w) };
        *(uint4*)&sB[0][ bR     * SSTR + bC] = u0;
        *(uint4*)&sB[0][(bR+8)  * SSTR + bC] = u1;
    }
    __syncthreads();

    constexpr int NK = K / BK;
    #pragma unroll 1
    for (int kt = 0; kt < NK; kt++) {
        int cur = kt & 1;
        // prefetch next tile
        if (kt + 1 < NK) {
            const float* An = Aptr + (size_t)(kt + 1) * BK;
            const float* Bn = Bptr + (size_t)(kt + 1) * BK * N;
            a0 = *(const float4*)(An);
            a1 = *(const float4*)(An + (size_t)64 * K);
            b0 = *(const float4*)(Bn);
            b1 = *(const float4*)(Bn + (size_t)8 * N);
        }

        // compute on current buffer
        #pragma unroll
        for (int ks = 0; ks < BK; ks += 8) {
            unsigned af[4][4];
            #pragma unroll
            for (int mt = 0; mt < 4; mt++) {
                int mb = wm + mt * 16 + gr;
                af[mt][0] = sA[cur][(ks + gc    ) * SSTR + mb    ];
                af[mt][1] = sA[cur][(ks + gc    ) * SSTR + mb + 8];
                af[mt][2] = sA[cur][(ks + gc + 4) * SSTR + mb    ];
                af[mt][3] = sA[cur][(ks + gc + 4) * SSTR + mb + 8];
            }
            unsigned bf[4][2];
            #pragma unroll
            for (int nt = 0; nt < 4; nt++) {
                int nb = wn + nt * 8 + gr;
                bf[nt][0] = sB[cur][(ks + gc    ) * SSTR + nb];
                bf[nt][1] = sB[cur][(ks + gc + 4) * SSTR + nb];
            }
            #pragma unroll
            for (int mt = 0; mt < 4; mt++)
                #pragma unroll
                for (int nt = 0; nt < 4; nt++)
                    mma_tf32(acc[mt][nt], af[mt], bf[nt]);
        }

        // stage next tile
        if (kt + 1 < NK) {
            int nxt = cur ^ 1;
            sA[nxt][(aC+0)*SSTR + aR]    = f2tf32(a0.x);
            sA[nxt][(aC+1)*SSTR + aR]    = f2tf32(a0.y);
            sA[nxt][(aC+2)*SSTR + aR]    = f2tf32(a0.z);
            sA[nxt][(aC+3)*SSTR + aR]    = f2tf32(a0.w);
            sA[nxt][(aC+0)*SSTR + aR+64] = f2tf32(a1.x);
            sA[nxt][(aC+1)*SSTR + aR+64] = f2tf32(a1.y);
            sA[nxt][(aC+2)*SSTR + aR+64] = f2tf32(a1.z);
            sA[nxt][(aC+3)*SSTR + aR+64] = f2tf32(a1.w);
            uint4 u0 = { f2tf32(b0.x), f2tf32(b0.y), f2tf32(b0.z), f2tf32(b0.w) };
            uint4 u1 = { f2tf32(b1.x), f2tf32(b1.y), f2tf32(b1.z), f2tf32(b1.w) };
            *(uint4*)&sB[nxt][ bR    * SSTR + bC] = u0;
            *(uint4*)&sB[nxt][(bR+8) * SSTR + bC] = u1;
        }
        __syncthreads();
    }

    // ---- epilogue ----
    #pragma unroll
    for (int mt = 0; mt < 4; mt++) {
        #pragma unroll
        for (int rh = 0; rh < 2; rh++) {
            int row = (int)blockM + wm + mt * 16 + gr + rh * 8;
            int orow = (MODE == 1) ? permuted_row(row) : row;
            #pragma unroll
            for (int nt = 0; nt < 4; nt++) {
                int col = blockN + wn + nt * 8 + gc * 2;
                float v0 = acc[mt][nt][rh * 2 + 0] + bias[col];
                float v1 = acc[mt][nt][rh * 2 + 1] + bias[col + 1];
                if (MODE == 1) {
                    float2 r2 = *(const float2*)(res + (size_t)orow * N + col);
                    v0 += r2.x; v1 += r2.y;
                } else if (MODE == 2) {
                    float y0 = v0, y1 = v1;
                    v0 = 0.5f * y0 * (1.f + tanhf(0.7978845608028654f * (y0 + 0.044715f * y0 * y0 * y0)));
                    v1 = 0.5f * y1 * (1.f + tanhf(0.7978845608028654f * (y1 + 0.044715f * y1 * y1 * y1)));
                } else if (MODE == 3) {
                    float2 r2 = *(const float2*)(res + (size_t)row * N + col);
                    v0 += r2.x; v1 += r2.y;
                }
                float2 o2 = { v0, v1 };
                *(float2*)(C + (size_t)orow * N + col) = o2;
            }
        }
    }
}

// ---------------- attention: one block per (window, head) ----------------
__global__ __launch_bounds__(256)
void attn_kernel(const float* __restrict__ qkv, const float* __restrict__ bias_table,
                 float* __restrict__ out)
{
    const int blk  = blockIdx.x;
    const int win  = blk >> 3;
    const int head = blk & 7;
    const int w    = win & 63;
    const int wy   = w >> 3, wx = w & 7;

    __shared__ float sq[NTOK * 33];
    __shared__ float sk[NTOK * 33];
    __shared__ float sv[NTOK * 33];
    __shared__ float S [NTOK * 50];
    __shared__ float sb[169];
    __shared__ int   sreg[NTOK];

    const int tid = threadIdx.x;

    for (int i = tid; i < 169; i += 256) sb[i] = bias_table[i * HEADS + head];
    if (tid < NTOK) {
        int r = tid / WS, c = tid - r * WS;
        int sy = wy * WS + r, sx = wx * WS + c;
        int ry = (sy < HDIM - WS) ? 0 : ((sy < HDIM - SS) ? 1 : 2);
        int rx = (sx < WDIM - WS) ? 0 : ((sx < WDIM - SS) ? 1 : 2);
        sreg[tid] = ry * 3 + rx;
    }

    const float scale = 0.17677669529663687f;  // 32^-0.5
    for (int i = tid; i < NTOK * HD; i += 256) {
        int n = i >> 5, dd = i & 31;
        const float* base = qkv + ((size_t)(win * NTOK + n)) * 768 + head * HD + dd;
        sq[n * 33 + dd] = base[0] * scale;
        sk[n * 33 + dd] = base[256];
        sv[n * 33 + dd] = base[512];
    }
    __syncthreads();

    for (int p = tid; p < NTOK * NTOK; p += 256) {
        int n1 = p / NTOK, n2 = p - n1 * NTOK;
        float s = 0.f;
        #pragma unroll
        for (int t = 0; t < HD; t++) s += sq[n1 * 33 + t] * sk[n2 * 33 + t];
        int r1 = n1 / WS, c1 = n1 - r1 * WS;
        int r2 = n2 / WS, c2 = n2 - r2 * WS;
        s += sb[(c1 - c2 + WS - 1) * (2 * WS - 1) + (r1 - r2 + WS - 1)];
        if (sreg[n1] != sreg[n2]) s -= 100.f;
        S[n1 * 50 + n2] = s;
    }
    __syncthreads();

    int warp = tid >> 5, lane = tid & 31;
    for (int n1 = warp; n1 < NTOK; n1 += 8) {
        float a0 = S[n1 * 50 + lane];
        float a1 = (lane + 32 < NTOK) ? S[n1 * 50 + lane + 32] : -1e30f;
        float m = fmaxf(a0, a1);
        #pragma unroll
        for (int o = 16; o > 0; o >>= 1) m = fmaxf(m, __shfl_xor_sync(0xffffffffu, m, o));
        float e0 = __expf(a0 - m);
        float e1 = (lane + 32 < NTOK) ? __expf(a1 - m) : 0.f;
        float ss = warp_sum(e0 + e1);
        float inv = 1.f / ss;
        S[n1 * 50 + lane] = e0 * inv;
        if (lane + 32 < NTOK) S[n1 * 50 + lane + 32] = e1 * inv;
    }
    __syncthreads();

    for (int p = tid; p < NTOK * HD; p += 256) {
        int n1 = p >> 5, dd = p & 31;
        float o = 0.f;
        #pragma unroll
        for (int j = 0; j < NTOK; j++) o += S[n1 * 50 + j] * sv[j * 33 + dd];
        out[((size_t)(win * NTOK + n1)) * CCH + head * HD + dd] = o;
    }
}

// ---------------- launch ----------------
extern "C" void kernel_launch(void* const* d_in, const int* in_sizes, int n_in,
                              void* d_out, int out_size)
{
    const float* x         = (const float*)d_in[0];
    const float* ln1_scale = (const float*)d_in[1];
    const float* ln1_bias  = (const float*)d_in[2];
    const float* qkv_w     = (const float*)d_in[3];
    const float* qkv_b     = (const float*)d_in[4];
    const float* proj_w    = (const float*)d_in[5];
    const float* proj_b    = (const float*)d_in[6];
    const float* bias_tbl  = (const float*)d_in[7];
    const float* ln2_scale = (const float*)d_in[8];
    const float* ln2_bias  = (const float*)d_in[9];
    const float* fc1_w     = (const float*)d_in[10];
    const float* fc1_b     = (const float*)d_in[11];
    const float* fc2_w     = (const float*)d_in[12];
    const float* fc2_b     = (const float*)d_in[13];
    float* out = (float*)d_out;

    float *xw, *qkv, *attn, *x2, *y2, *hbuf;
    cudaGetSymbolAddress((void**)&xw,   g_xw);
    cudaGetSymbolAddress((void**)&qkv,  g_qkv);
    cudaGetSymbolAddress((void**)&attn, g_attn);
    cudaGetSymbolAddress((void**)&x2,   g_x2);
    cudaGetSymbolAddress((void**)&y2,   g_y2);
    cudaGetSymbolAddress((void**)&hbuf, g_h);

    dim3 lnBlk(32, 8);
    int  lnGrid = ROWS / 8;

    // 1. LN1 + shift + window partition
    ln_kernel<<<lnGrid, lnBlk>>>(x, ln1_scale, ln1_bias, xw, 1);
    // 2. QKV gemm: (100352 x 256) @ (256 x 768)
    mma_gemm<0, 768, 256><<<dim3(768 / 128, ROWS / 128), 256>>>(xw, qkv_w, qkv_b, nullptr, qkv);
    // 3. attention per (window, head)
    attn_kernel<<<NWIN * HEADS, 256>>>(qkv, bias_tbl, attn);
    // 4. proj gemm + window reverse + unshift + residual -> x2 (image layout)
    mma_gemm<1, 256, 256><<<dim3(256 / 128, ROWS / 128), 256>>>(attn, proj_w, proj_b, x, x2);
    // 5. LN2
    ln_kernel<<<lnGrid, lnBlk>>>(x2, ln2_scale, ln2_bias, y2, 0);
    // 6. fc1 + gelu
    mma_gemm<2, 1024, 256><<<dim3(1024 / 128, ROWS / 128), 256>>>(y2, fc1_w, fc1_b, nullptr, hbuf);
    // 7. fc2 + residual -> out
    mma_gemm<3, 256, 1024><<<dim3(256 / 128, ROWS / 128), 256>>>(hbuf, fc2_w, fc2_b, x2, out);
}